// round 12
// baseline (speedup 1.0000x reference)
#include <cuda_runtime.h>
#include <stdint.h>
#include <math.h>

#define B_ 8
#define C_ 64
#define L_ 2048
#define CS_ 256
#define HD_ 64
#define NN_ (B_*CS_*L_)      // 4194304
#define NC_ (B_*C_*L_)       // 1048576
#define NEVAL_ 25
#define LT_ 56               // l-tile per block
#define NBX_ 37              // 37*56 = 2072 >= 2048

// kfused smem layout (floats):
// XS: [0, 8192)    (half*2 + buf)*2048
// H1: [8192,16384) half*4096, row stride 64
// H2: [16384,24576)
// WQ: [24576, 49152) as ull: 4 slots x 3072 ull (24KB each)
#define SMB2 (49152*4)       // 196608 B = 192KB

// packed weights: ONE contiguous stream of 18 parts x 3072 ull
// parts 0-7: w1 (256ci), 8-9: w2 (64ci), 10-17: w3 (4g x 64ci)
#define WPTOT 55296

typedef unsigned long long ull;

__device__ float g_stacked[NN_];
__device__ float g_y[NN_];
__device__ float g_y2[NN_];
__device__ float g_s[6][NN_];
__device__ float g_apA[NC_];
__device__ float g_apB[NC_];
__device__ float g_amax[B_*C_];
__device__ float g_filt[16];
__device__ float g_gb[NEVAL_*128];
__device__ double g_part[B_*64];
__device__ int   g_ctr = 0;
__device__ __align__(16) ull g_wp[WPTOT];

__device__ __forceinline__ float gelu_f(float x){
    return 0.5f * x * (1.0f + erff(x * 0.70710678118654752440f));
}
__device__ __forceinline__ ull bcast2(float x){
    ull r; asm("mov.b64 %0, {%1, %1};" : "=l"(r) : "f"(x)); return r;
}
__device__ __forceinline__ ull pk2(float a, float b){
    ull r; asm("mov.b64 %0, {%1, %2};" : "=l"(r) : "f"(a), "f"(b)); return r;
}
__device__ __forceinline__ void fma2(ull &d, ull a, ull b){
    asm("fma.rn.f32x2 %0, %1, %2, %0;" : "+l"(d) : "l"(a), "l"(b));
}
__device__ __forceinline__ float2 unpk(ull v){
    float lo, hi; asm("mov.b64 {%0, %1}, %2;" : "=f"(lo), "=f"(hi) : "l"(v));
    return make_float2(lo, hi);
}

// ---------------- dywan MLP tail (whole block, 256 threads) ----------------
__device__ void dywan_tail(const float* __restrict__ amax,
                           const float* __restrict__ sw1, const float* __restrict__ sb1,
                           const float* __restrict__ sw2, const float* __restrict__ sb2,
                           const float* __restrict__ sw3, const float* __restrict__ sb3,
                           float* __restrict__ filtOut){
    __shared__ float feat[256], g2s[256], raw[128], nrm[16];
    int t = threadIdx.x;
    { int bb = t >> 5, h = t & 31;
      float s = sb1[h];
      const float* am = amax + bb*64; const float* w = sw1 + h*64;
      #pragma unroll 8
      for (int c = 0; c < 64; c++) s += am[c]*w[c];
      feat[t] = gelu_f(s); }
    __syncthreads();
    { int bb = t >> 5, h = t & 31;
      float s = sb2[h];
      #pragma unroll 8
      for (int k = 0; k < 32; k++) s += feat[bb*32+k]*sw2[h*32+k];
      g2s[t] = gelu_f(s); }
    __syncthreads();
    if (t < 128){ int bb = t >> 4, j = t & 15;
      float s = sb3[j];
      #pragma unroll 8
      for (int k = 0; k < 32; k++) s += g2s[bb*32+k]*sw3[j*32+k];
      raw[t] = s; }
    __syncthreads();
    if (t < 16){ int bb = t >> 1, hh = t & 1;
      float s = 0.f;
      for (int j = 0; j < 8; j++){ float v = raw[bb*16 + hh*8 + j]; s += v*v; }
      nrm[t] = sqrtf(s); }
    __syncthreads();
    if (t < 16){ int hh = t >> 3, j = t & 7;
      float s = 0.f;
      for (int bb = 0; bb < 8; bb++) s += raw[bb*16 + hh*8 + j] / nrm[bb*2 + hh];
      filtOut[hh*8 + j] = s * 0.125f; }
}

// ---------------- kprep: amax rows 0-511, gb 512-536, spin-dywan 537, weight-pack 538+ ----------------
__global__ void kprep(const float* __restrict__ x,
                      const float* __restrict__ tw1, const float* __restrict__ tb1,
                      const float* __restrict__ tw2, const float* __restrict__ tb2,
                      const float* __restrict__ cw,  const float* __restrict__ cb,
                      const float* __restrict__ sw1, const float* __restrict__ sb1,
                      const float* __restrict__ sw2, const float* __restrict__ sb2,
                      const float* __restrict__ sw3, const float* __restrict__ sb3,
                      const float* __restrict__ w1, const float* __restrict__ w2,
                      const float* __restrict__ w3,
                      float* __restrict__ amax, float* __restrict__ gbout,
                      float* __restrict__ filt, ull* __restrict__ wp,
                      int* __restrict__ ctr){
    int t = threadIdx.x;
    if (blockIdx.x < 512){
        int row = blockIdx.x;
        const float* p = x + (size_t)row * L_;
        float m = -3.4e38f;
        for (int i = t; i < L_; i += 256) m = fmaxf(m, p[i]);
        __shared__ float sm[256];
        sm[t] = m; __syncthreads();
        for (int s = 128; s > 0; s >>= 1){
            if (t < s) sm[t] = fmaxf(sm[t], sm[t+s]);
            __syncthreads();
        }
        if (t == 0){
            amax[row] = sm[0];
            __threadfence();
            atomicAdd(ctr, 1);
        }
    } else if (blockIdx.x < 537){
        int e = blockIdx.x - 512;
        const double hs = 0.25;
        double td;
        if (e == 24) td = 1.0;
        else {
            int i = e / 6, s = e % 6;
            double off;
            switch (s){
                case 0: off = 0.0; break;
                case 1: off = hs/5.0; break;
                case 2: off = 3.0*hs/10.0; break;
                case 3: off = 4.0*hs/5.0; break;
                case 4: off = 8.0*hs/9.0; break;
                default: off = hs; break;
            }
            td = (double)i*hs + off;
        }
        float tt = (float)td;
        __shared__ float te1[16], te2[16];
        if (t < 16) te1[t] = gelu_f(tt * tw1[t] + tb1[t]);
        __syncthreads();
        if (t < 16){
            float s = tb2[t];
            #pragma unroll
            for (int k = 0; k < 16; k++) s += te1[k]*tw2[t*16+k];
            te2[t] = s;
        }
        __syncthreads();
        if (t < 128){
            float s = cb[t];
            #pragma unroll
            for (int k = 0; k < 16; k++) s += te2[k]*cw[t*16+k];
            gbout[e*128 + t] = s;
        }
    } else if (blockIdx.x == 537){
        if (t == 0){
            while (atomicAdd(ctr, 0) < 512) __nanosleep(200);
        }
        __syncthreads();
        __threadfence();
        dywan_tail(amax, sw1, sb1, sw2, sb2, sw3, sb3, filt);
        __syncthreads();
        if (t == 0) atomicExch(ctr, 0);
    } else {
        int idx = (blockIdx.x - 538)*256 + t;
        if (idx >= WPTOT) return;
        float wa, wb;
        if (idx < 24576){
            int ci = idx / 96, r = idx - ci*96;
            int k = r >> 5, p = r & 31;
            wa = w1[(size_t)(2*p)  *(CS_*3) + ci*3 + k];
            wb = w1[(size_t)(2*p+1)*(CS_*3) + ci*3 + k];
        } else if (idx < 30720){
            int j = idx - 24576;
            int ci = j / 96, r = j - ci*96;
            int k = r >> 5, p = r & 31;
            wa = w2[(size_t)(2*p)  *(HD_*3) + ci*3 + k];
            wb = w2[(size_t)(2*p+1)*(HD_*3) + ci*3 + k];
        } else {
            int j = idx - 30720;
            int g = j / 6144, r2 = j - g*6144;
            int ci = r2 / 96, r = r2 - ci*96;
            int k = r >> 5, p = r & 31;
            wa = w3[(size_t)(g*64 + 2*p)  *(HD_*3) + ci*3 + k];
            wb = w3[(size_t)(g*64 + 2*p+1)*(HD_*3) + ci*3 + k];
        }
        wp[idx] = pk2(wa, wb);
    }
}

// ---------------- kwavF: per-row wavelet conv + row-max + optional next-level dywan ----------------
__global__ void kwavF(const float* __restrict__ src,
                      const float* __restrict__ filtIn,
                      float* __restrict__ apOut, float* __restrict__ stacked,
                      float* __restrict__ amaxNext, int chOff, int copyX, int computeNext,
                      const float* __restrict__ sw1, const float* __restrict__ sb1,
                      const float* __restrict__ sw2, const float* __restrict__ sb2,
                      const float* __restrict__ sw3, const float* __restrict__ sb3,
                      float* __restrict__ filtOut, int* __restrict__ ctr){
    __shared__ float xr[2064];
    __shared__ float red[256];
    __shared__ int lastFlag;
    int t = threadIdx.x;
    int r = blockIdx.x;
    int b = r >> 6, c = r & 63;
    const float* row = src + (size_t)r * L_;

    float f[16];
    #pragma unroll
    for (int i = 0; i < 16; i++) f[i] = filtIn[i];

    for (int s = t; s < 2056; s += 256){
        int gl = s - 3;
        if (gl < 0) gl = -gl;
        if (gl >= L_) gl = 2*L_ - 2 - gl;
        xr[s] = row[gl];
    }
    __syncthreads();

    int l0 = t * 8;
    float xv[16];
    #pragma unroll
    for (int i = 0; i < 4; i++)
        *(float4*)&xv[i*4] = *(const float4*)&xr[l0 + i*4];

    float alo[8], ahi[8];
    float mlo = -3.4e38f;
    #pragma unroll
    for (int j = 0; j < 8; j++){
        float a = 0.f, h = 0.f;
        #pragma unroll
        for (int k = 0; k < 8; k++){
            float v = (j + k < 15) ? xv[j+k] : xr[l0 + j + k];
            a += v * f[k];
            h += v * f[8+k];
        }
        alo[j] = a; ahi[j] = h;
        mlo = fmaxf(mlo, a);
    }
    *(float4*)&apOut[(size_t)r*L_ + l0]     = *(float4*)&alo[0];
    *(float4*)&apOut[(size_t)r*L_ + l0 + 4] = *(float4*)&alo[4];
    float* st = stacked + (((size_t)b*CS_ + chOff + c) << 11) + l0;
    *(float4*)&st[0] = *(float4*)&ahi[0];
    *(float4*)&st[4] = *(float4*)&ahi[4];
    if (copyX){
        float* sx = stacked + (((size_t)b*CS_ + c) << 11) + l0;
        #pragma unroll
        for (int j = 0; j < 8; j++) sx[j] = xr[l0 + 3 + j];
    }
    red[t] = mlo; __syncthreads();
    for (int s = 128; s > 0; s >>= 1){
        if (t < s) red[t] = fmaxf(red[t], red[t+s]);
        __syncthreads();
    }
    if (t == 0) amaxNext[r] = red[0];

    if (computeNext){
        __syncthreads();
        if (t == 0){
            __threadfence();
            int old = atomicAdd(ctr, 1);
            lastFlag = (old == 511) ? 1 : 0;
        }
        __syncthreads();
        if (lastFlag){
            __threadfence();
            dywan_tail(amaxNext, sw1, sb1, sw2, sb2, sw3, sb3, filtOut);
            __syncthreads();
            if (t == 0) atomicExch(ctr, 0);
        }
    }
}

// ---------------- fused ode_f core: 4co x 4l per thread, 32-ci parts ----------------
// register-lean form: each broadcast temp is created and immediately consumed.
// per-acc accumulation order is k = 0,1,2 (same as before) -> bit-identical.
__device__ __forceinline__ void acc_run32(const float* __restrict__ xsm,
                                          const ull* __restrict__ wsp,
                                          int cp0, int l0, ull acc[2][4]){
    #pragma unroll 2
    for (int ci = 0; ci < 32; ci++){
        const float* xr = xsm + ci*64 + l0;
        float4 xa = *(const float4*)xr;
        float2 xb = *(const float2*)(xr + 4);
        const ull* wr = wsp + ci*96 + cp0;
        ulonglong2 w0 = *(const ulonglong2*)(wr);
        ulonglong2 w1 = *(const ulonglong2*)(wr + 32);
        ulonglong2 w2 = *(const ulonglong2*)(wr + 64);
        float xs6[6] = {xa.x, xa.y, xa.z, xa.w, xb.x, xb.y};
        #pragma unroll
        for (int j = 0; j < 6; j++){
            ull qj = bcast2(xs6[j]);
            if (j < 4){           fma2(acc[0][j],   w0.x, qj); fma2(acc[1][j],   w0.y, qj); }
            if (j >= 1 && j < 5){ fma2(acc[0][j-1], w1.x, qj); fma2(acc[1][j-1], w1.y, qj); }
            if (j >= 2){          fma2(acc[0][j-2], w2.x, qj); fma2(acc[1][j-2], w2.y, qj); }
        }
    }
}

// grid (37, 4), 512 threads; half = t>>8 owns batch row b = 2*by + half.
// within half: ct = tl>>4 (16 co-groups x 4co), lt = tl&15 (4 l per thread).
// weight stream: 18 parts x 24KB through a 4-slot cp.async ring (depth 3).
// slots: x 62 valid (gl=L0-3+j), h1 60 (gl=L0-2+i), h2 58 (gl=L0-1+i), out 56.
template<int NA, bool YC>
__global__ __launch_bounds__(512, 1)
void kfused(const float* __restrict__ y,
            const float* __restrict__ a1, float c1,
            const float* __restrict__ a2, float c2,
            const float* __restrict__ a3, float c3,
            const float* __restrict__ a4, float c4,
            const float* __restrict__ a5, float c5,
            const ull* __restrict__ wp,
            const float* __restrict__ b1v, const float* __restrict__ b2v,
            const float* __restrict__ b3v,
            const float* __restrict__ gb,
            float* __restrict__ youtg, float* __restrict__ outp){
    extern __shared__ float sm[];
    const int t    = threadIdx.x;
    const int half = t >> 8;
    const int tl   = t & 255;
    const int ct   = tl >> 4;
    const int lt   = tl & 15;
    const int co0  = ct * 4;
    const int cp0  = ct * 2;
    const int l0a  = lt * 4;
    const int b    = blockIdx.y*2 + half;
    const int L0   = blockIdx.x * LT_;

    float* xsh = sm + half*4096;            // 2 bufs x 2048 per half
    float* h1s = sm + 8192  + half*4096;
    float* h2s = sm + 16384 + half*4096;
    ull*   wq  = (ull*)(sm + 24576);

    unsigned int smbase;
    asm("{ .reg .u64 tt; cvta.to.shared.u64 tt, %1; cvt.u32.u64 %0, tt; }"
        : "=r"(smbase) : "l"(sm));
    const unsigned int smW = smbase + 24576u*4u;

    const size_t inOff = (size_t)b * CS_ * L_;
    const float* yb = y + inOff;
    const float* p1 = (NA>=1) ? (a1 + inOff) : yb;
    const float* p2 = (NA>=2) ? (a2 + inOff) : yb;
    const float* p3 = (NA>=3) ? (a3 + inOff) : yb;
    const float* p4 = (NA>=4) ? (a4 + inOff) : yb;
    const float* p5 = (NA>=5) ? (a5 + inOff) : yb;
    float* youtb = YC ? (youtg + inOff) : nullptr;

    auto loadX = [&](int c0, int buf){
        float* dst = xsh + buf*2048;
        #pragma unroll
        for (int rr = 0; rr < 8; rr++){
            int idx = tl + rr*256;
            int ci = idx >> 6, j = idx & 63;
            int gl = L0 - 3 + j;
            float v = 0.f;
            if (j < 62 && ((unsigned)gl < (unsigned)L_)){
                size_t o = (size_t)(c0 + ci) * L_ + (size_t)gl;
                v = yb[o];
                if (NA>=1) v = fmaf(c1, p1[o], v);
                if (NA>=2) v = fmaf(c2, p2[o], v);
                if (NA>=3) v = fmaf(c3, p3[o], v);
                if (NA>=4) v = fmaf(c4, p4[o], v);
                if (NA>=5) v = fmaf(c5, p5[o], v);
                if (YC){ if (j >= 3 && j < 59) youtb[o] = v; }
            }
            dst[idx] = v;
        }
    };
    auto issueW = [&](int p){
        const char* src = (const char*)(wp + (size_t)p * 3072);
        unsigned int dbase = smW + (unsigned int)((p & 3) * 3072) * 8u;
        #pragma unroll
        for (int i = 0; i < 3; i++){
            int idx = t + i*512;
            asm volatile("cp.async.cg.shared.global [%0], [%1], 16;"
                :: "r"(dbase + (unsigned int)idx*16u), "l"(src + (size_t)idx*16));
        }
        asm volatile("cp.async.commit_group;");
    };

    issueW(0); issueW(1); issueW(2);
    loadX(0, 0);

    ull acc[2][4];
    const int l1c = min(l0a, 56);
    const int l3c = min(l0a, 52);

    #pragma unroll 1
    for (int p = 0; p < 18; p++){
        if (p < 16)       asm volatile("cp.async.wait_group 2;");
        else if (p == 16) asm volatile("cp.async.wait_group 1;");
        else              asm volatile("cp.async.wait_group 0;");
        __syncthreads();
        if (p + 3 < 18) issueW(p + 3);
        if (p < 7) loadX((p+1)*32, (p+1)&1);

        if (p == 0 || p == 8 || p == 10 || p == 12 || p == 14 || p == 16){
            #pragma unroll
            for (int a = 0; a < 2; a++)
                #pragma unroll
                for (int l = 0; l < 4; l++) acc[a][l] = 0ULL;
        }

        const ull* wslot = wq + (p & 3) * 3072;
        const float* xin;
        int lc;
        if (p < 8)      { xin = xsh + (p&1)*2048;        lc = l1c; }
        else if (p < 10){ xin = h1s + (p-8)*2048;        lc = l1c; }   // l2c == l1c == min(l0a,56)
        else            { xin = h2s + ((p-10)&1)*2048;   lc = l3c; }
        acc_run32(xin, wslot, cp0, lc, acc);

        if (p == 7){
            // epilogue 1: bias + FiLM + GELU -> h1 (zero outside [0,L))
            float v[4][4];
            #pragma unroll
            for (int l = 0; l < 4; l++){
                float2 u0 = unpk(acc[0][l]), u1 = unpk(acc[1][l]);
                v[0][l]=u0.x; v[1][l]=u0.y; v[2][l]=u1.x; v[3][l]=u1.y;
            }
            #pragma unroll
            for (int cc = 0; cc < 4; cc++){
                int co = co0 + cc;
                float bia = b1v[co], ga = 1.f + gb[co], be = gb[64+co];
                float4 r;
                float* pr = (float*)&r;
                #pragma unroll
                for (int ll = 0; ll < 4; ll++){
                    int gl = L0 - 2 + l1c + ll;
                    float h = gelu_f(ga*(v[cc][ll]+bia)+be);
                    pr[ll] = ((unsigned)gl < (unsigned)L_) ? h : 0.f;
                }
                *(float4*)&h1s[co*64 + l1c] = r;
            }
        } else if (p == 9){
            // epilogue 2: bias + GELU -> h2 (zero outside [0,L))
            float v[4][4];
            #pragma unroll
            for (int l = 0; l < 4; l++){
                float2 u0 = unpk(acc[0][l]), u1 = unpk(acc[1][l]);
                v[0][l]=u0.x; v[1][l]=u0.y; v[2][l]=u1.x; v[3][l]=u1.y;
            }
            #pragma unroll
            for (int cc = 0; cc < 4; cc++){
                int co = co0 + cc;
                float bia = b2v[co];
                float4 r;
                float* pr = (float*)&r;
                #pragma unroll
                for (int ll = 0; ll < 4; ll++){
                    int gl = L0 - 1 + l1c + ll;
                    float h = gelu_f(v[cc][ll]+bia);
                    pr[ll] = ((unsigned)gl < (unsigned)L_) ? h : 0.f;
                }
                *(float4*)&h2s[co*64 + l1c] = r;
            }
        } else if (p >= 11 && (p & 1)){
            // stage-3 output for group g
            int g = (p - 11) >> 1;
            int gl0 = L0 + l3c;
            if (gl0 < L_){
                float v[4][4];
                #pragma unroll
                for (int l = 0; l < 4; l++){
                    float2 u0 = unpk(acc[0][l]), u1 = unpk(acc[1][l]);
                    v[0][l]=u0.x; v[1][l]=u0.y; v[2][l]=u1.x; v[3][l]=u1.y;
                }
                #pragma unroll
                for (int cc = 0; cc < 4; cc++){
                    int co = g*64 + co0 + cc;
                    float bia = b3v[co];
                    float4 r = make_float4(v[cc][0]+bia, v[cc][1]+bia,
                                           v[cc][2]+bia, v[cc][3]+bia);
                    *(float4*)&outp[((size_t)(b*CS_ + co))*L_ + gl0] = r;
                }
            }
        }
    }
}

// ---------------- ecloss reduction ----------------
__global__ void kinner(const float* __restrict__ a, const float* __restrict__ d,
                       double* __restrict__ part){
    int bb = blockIdx.x, ch = blockIdx.y;
    size_t base = (size_t)bb*CS_*L_ + (size_t)ch*8192;
    double s = 0.0;
    for (int i = threadIdx.x; i < 8192; i += 256)
        s += (double)a[base+i] * (double)d[base+i];
    __shared__ double sm[256];
    sm[threadIdx.x] = s; __syncthreads();
    for (int st = 128; st > 0; st >>= 1){
        if (threadIdx.x < st) sm[threadIdx.x] += sm[threadIdx.x+st];
        __syncthreads();
    }
    if (threadIdx.x == 0) part[bb*64 + ch] = sm[0];
}

__global__ void kfinal(const double* __restrict__ part, float* __restrict__ out){
    if (threadIdx.x == 0){
        double acc = 0.0;
        for (int b = 0; b < 8; b++){
            double s = 0.0;
            for (int j = 0; j < 64; j++) s += part[b*64+j];
            acc += s*s;
        }
        out[4194304] = (float)(acc / 8.0);
    }
}

// ---------------- output permute ----------------
__global__ void kout(const float* __restrict__ y, float* __restrict__ out){
    int i = blockIdx.x*256 + threadIdx.x;
    int l = i & (L_-1); int bc = i >> 11; int c = bc & 255; int b = bc >> 8;
    int g = c >> 6; int cc = c & 63;
    out[(size_t)g*(B_*C_*L_) + (((size_t)b*C_ + cc) << 11) + l] = y[i];
}

// ---------------- host orchestration ----------------
extern "C" void kernel_launch(void* const* d_in, const int* in_sizes, int n_in,
                              void* d_out, int out_size){
    const float* x   = (const float*)d_in[0];
    const float* sw1 = (const float*)d_in[1];
    const float* sb1 = (const float*)d_in[2];
    const float* sw2 = (const float*)d_in[3];
    const float* sb2 = (const float*)d_in[4];
    const float* sw3 = (const float*)d_in[5];
    const float* sb3 = (const float*)d_in[6];
    const float* tw1 = (const float*)d_in[7];
    const float* tb1 = (const float*)d_in[8];
    const float* tw2 = (const float*)d_in[9];
    const float* tb2 = (const float*)d_in[10];
    const float* cw  = (const float*)d_in[11];
    const float* cb  = (const float*)d_in[12];
    const float* k1  = (const float*)d_in[13];
    const float* kb1 = (const float*)d_in[14];
    const float* k2  = (const float*)d_in[15];
    const float* kb2 = (const float*)d_in[16];
    const float* k3  = (const float*)d_in[17];
    const float* kb3 = (const float*)d_in[18];
    float* out = (float*)d_out;

    float *stacked, *y, *y2, *sbase, *apA, *apB, *amax, *filt, *gb;
    double* part; int* ctr; ull* wp;
    cudaGetSymbolAddress((void**)&stacked, g_stacked);
    cudaGetSymbolAddress((void**)&y,       g_y);
    cudaGetSymbolAddress((void**)&y2,      g_y2);
    cudaGetSymbolAddress((void**)&sbase,   g_s);
    cudaGetSymbolAddress((void**)&apA,     g_apA);
    cudaGetSymbolAddress((void**)&apB,     g_apB);
    cudaGetSymbolAddress((void**)&amax,    g_amax);
    cudaGetSymbolAddress((void**)&filt,    g_filt);
    cudaGetSymbolAddress((void**)&gb,      g_gb);
    cudaGetSymbolAddress((void**)&part,    g_part);
    cudaGetSymbolAddress((void**)&ctr,     g_ctr);
    cudaGetSymbolAddress((void**)&wp,      g_wp);

    cudaFuncSetAttribute(kfused<0,false>, cudaFuncAttributeMaxDynamicSharedMemorySize, SMB2);
    cudaFuncSetAttribute(kfused<1,false>, cudaFuncAttributeMaxDynamicSharedMemorySize, SMB2);
    cudaFuncSetAttribute(kfused<2,false>, cudaFuncAttributeMaxDynamicSharedMemorySize, SMB2);
    cudaFuncSetAttribute(kfused<3,false>, cudaFuncAttributeMaxDynamicSharedMemorySize, SMB2);
    cudaFuncSetAttribute(kfused<4,false>, cudaFuncAttributeMaxDynamicSharedMemorySize, SMB2);
    cudaFuncSetAttribute(kfused<5,false>, cudaFuncAttributeMaxDynamicSharedMemorySize, SMB2);
    cudaFuncSetAttribute(kfused<5,true >, cudaFuncAttributeMaxDynamicSharedMemorySize, SMB2);

    float* S[6];
    for (int k = 0; k < 6; k++) S[k] = sbase + (size_t)k * NN_;

    // ---- prologue: 4 launches ----
    kprep<<<754, 256>>>(x, tw1, tb1, tw2, tb2, cw, cb,
                        sw1, sb1, sw2, sb2, sw3, sb3, k1, k2, k3,
                        amax, gb, filt, wp, ctr);
    kwavF<<<512, 256>>>(x,   filt, apA, stacked, amax, 64,  1, 1,
                        sw1, sb1, sw2, sb2, sw3, sb3, filt, ctr);
    kwavF<<<512, 256>>>(apA, filt, apB, stacked, amax, 128, 0, 1,
                        sw1, sb1, sw2, sb2, sw3, sb3, filt, ctr);
    kwavF<<<512, 256>>>(apB, filt, apA, stacked, amax, 192, 0, 0,
                        sw1, sb1, sw2, sb2, sw3, sb3, filt, ctr);

    const dim3 gF(NBX_, 4);
    const double hs = 0.25;
    const float* Z = nullptr;

    auto ev_plain = [&](int ev, int na, const float* ybase,
                        const float* a1, float c1, const float* a2, float c2,
                        const float* a3, float c3, const float* a4, float c4,
                        const float* a5, float c5, float* sout){
        const float* gbe = gb + ev*128;
        switch (na){
        case 0: kfused<0,false><<<gF,512,SMB2>>>(ybase,a1,c1,a2,c2,a3,c3,a4,c4,a5,c5,wp,kb1,kb2,kb3,gbe,nullptr,sout); break;
        case 1: kfused<1,false><<<gF,512,SMB2>>>(ybase,a1,c1,a2,c2,a3,c3,a4,c4,a5,c5,wp,kb1,kb2,kb3,gbe,nullptr,sout); break;
        case 2: kfused<2,false><<<gF,512,SMB2>>>(ybase,a1,c1,a2,c2,a3,c3,a4,c4,a5,c5,wp,kb1,kb2,kb3,gbe,nullptr,sout); break;
        case 3: kfused<3,false><<<gF,512,SMB2>>>(ybase,a1,c1,a2,c2,a3,c3,a4,c4,a5,c5,wp,kb1,kb2,kb3,gbe,nullptr,sout); break;
        case 4: kfused<4,false><<<gF,512,SMB2>>>(ybase,a1,c1,a2,c2,a3,c3,a4,c4,a5,c5,wp,kb1,kb2,kb3,gbe,nullptr,sout); break;
        default:kfused<5,false><<<gF,512,SMB2>>>(ybase,a1,c1,a2,c2,a3,c3,a4,c4,a5,c5,wp,kb1,kb2,kb3,gbe,nullptr,sout); break;
        }
    };
    auto ev_ycomb = [&](int ev, const float* ybase, float** M, float* yout, float* sout){
        kfused<5,true><<<gF,512,SMB2>>>(ybase,
            M[0],(float)(hs*35.0/384.0), M[2],(float)(hs*500.0/1113.0),
            M[3],(float)(hs*125.0/192.0), M[4],(float)(-hs*2187.0/6784.0),
            M[5],(float)(hs*11.0/84.0),
            wp, kb1, kb2, kb3, gb + ev*128, yout, sout);
    };

    float* MA[6] = {S[0],S[1],S[2],S[3],S[4],S[5]};
    float* MB[6] = {S[1],S[0],S[2],S[3],S[4],S[5]};

    auto step_tail = [&](int e, const float* ybase, float** M){
        ev_plain(e+1, 1, ybase, M[0],(float)(hs*1.0/5.0), Z,0,Z,0,Z,0,Z,0, M[1]);
        ev_plain(e+2, 2, ybase, M[0],(float)(hs*3.0/40.0), M[1],(float)(hs*9.0/40.0), Z,0,Z,0,Z,0, M[2]);
        ev_plain(e+3, 3, ybase, M[0],(float)(hs*44.0/45.0), M[1],(float)(-hs*56.0/15.0),
                 M[2],(float)(hs*32.0/9.0), Z,0,Z,0, M[3]);
        ev_plain(e+4, 4, ybase, M[0],(float)(hs*19372.0/6561.0), M[1],(float)(-hs*25360.0/2187.0),
                 M[2],(float)(hs*64448.0/6561.0), M[3],(float)(-hs*212.0/729.0), Z,0, M[4]);
        ev_plain(e+5, 5, ybase, M[0],(float)(hs*9017.0/3168.0), M[1],(float)(-hs*355.0/33.0),
                 M[2],(float)(hs*46732.0/5247.0), M[3],(float)(hs*49.0/176.0),
                 M[4],(float)(-hs*5103.0/18656.0), M[5]);
    };

    ev_plain(0, 0, stacked, Z,0,Z,0,Z,0,Z,0,Z,0, MA[0]);
    step_tail(0, stacked, MA);
    ev_ycomb(6, stacked, MA, y, MB[0]);
    step_tail(6, y, MB);
    ev_ycomb(12, y, MB, y2, MA[0]);
    step_tail(12, y2, MA);
    ev_ycomb(18, y2, MA, y, MB[0]);
    step_tail(18, y, MB);
    ev_ycomb(24, y, MB, y2, S[0]);

    kinner<<<dim3(B_, 64), 256>>>(stacked, S[0], part);
    kout<<<NN_/256, 256>>>(y2, out);
    kfinal<<<1, 32>>>(part, out);
}